// round 1
// baseline (speedup 1.0000x reference)
#include <cuda_runtime.h>
#include <math.h>

// SimpleLSTM fused kernel: 2 stacked LSTMs (F=32 -> H=64 -> H=64) + Dense(64,sigmoid) + Dense(1,sigmoid)
// B=4096, T=256. Each block owns BB=8 batch rows and runs the whole time loop locally.
// Weights U1, W2, U2 cached in shared memory ([K][4H] row-major -> stride-1 across threads).
// W1 column + biases live in registers per thread.

#define T_STEPS 256
#define F_IN    32
#define HU      64
#define G4      256     // 4*H
#define BB      8       // batch rows per block
#define NTH     512

__device__ __forceinline__ float sigf(float v) {
    return 1.0f / (1.0f + __expf(-v));
}

__global__ void __launch_bounds__(NTH, 1)
lstm_fused_kernel(const float* __restrict__ x,
                  const float* __restrict__ W1,
                  const float* __restrict__ U1,
                  const float* __restrict__ b1,
                  const float* __restrict__ W2,
                  const float* __restrict__ U2,
                  const float* __restrict__ b2,
                  const float* __restrict__ Wd,
                  const float* __restrict__ bd,
                  const float* __restrict__ Wo,
                  const float* __restrict__ bo,
                  float* __restrict__ out)
{
    extern __shared__ float smem[];
    float* U1s = smem;                    // 64*256
    float* W2s = U1s + HU * G4;           // 64*256
    float* U2s = W2s + HU * G4;           // 64*256
    float* zs  = U2s + HU * G4;           // BB*256
    float* h1s = zs  + BB * G4;           // BB*64
    float* h2s = h1s + BB * HU;           // BB*64
    float* xs  = h2s + BB * HU;           // BB*32
    float* ds  = xs  + BB * F_IN;         // BB*64

    const int tid = threadIdx.x;
    const int bb0 = blockIdx.x * BB;

    // ---- load recurrent/weight matrices into smem (float4, coalesced) ----
    {
        const int n4 = (HU * G4) / 4;     // 4096 float4 per matrix
        const float4* s1 = (const float4*)U1;
        const float4* s2 = (const float4*)W2;
        const float4* s3 = (const float4*)U2;
        float4* d1 = (float4*)U1s;
        float4* d2 = (float4*)W2s;
        float4* d3 = (float4*)U2s;
        for (int i = tid; i < n4; i += NTH) {
            d1[i] = s1[i];
            d2[i] = s2[i];
            d3[i] = s3[i];
        }
    }
    // zero states
    for (int i = tid; i < BB * HU; i += NTH) { h1s[i] = 0.0f; h2s[i] = 0.0f; }

    // ---- per-thread column assignment for gate pre-activations ----
    const int j     = tid & 255;              // gate column 0..255
    const int bhalf = (tid >> 8) * (BB / 2);  // first or second half of batch tile

    float w1c[F_IN];
#pragma unroll
    for (int k = 0; k < F_IN; k++) w1c[k] = W1[k * G4 + j];
    const float b1j = b1[j];
    const float b2j = b2[j];

    // ---- per-thread state-update assignment (512 = 8 batch * 64 units) ----
    const int ub = tid >> 6;     // batch row in tile 0..7
    const int uj = tid & 63;     // hidden unit 0..63
    float c1 = 0.0f, c2 = 0.0f;

    __syncthreads();

    const long long xbase = (long long)bb0 * T_STEPS * F_IN;

    for (int t = 0; t < T_STEPS; t++) {
        // ---- stage x_t for the batch tile (64 threads, one float4 each) ----
        if (tid < BB * F_IN / 4) {
            int b  = tid >> 3;          // 8 float4 per batch row
            int f4 = tid & 7;
            ((float4*)xs)[tid] =
                *(const float4*)(x + xbase + ((long long)b * T_STEPS + t) * F_IN + f4 * 4);
        }
        __syncthreads();

        // ---- phase 1: z1 = x_t @ W1 + h1 @ U1 + b1 ----
        {
            float acc[BB / 2];
#pragma unroll
            for (int b = 0; b < BB / 2; b++) acc[b] = b1j;

            // input contribution (W1 column in registers)
#pragma unroll
            for (int b = 0; b < BB / 2; b++) {
                const float4* xv = (const float4*)(xs + (bhalf + b) * F_IN);
#pragma unroll
                for (int k4 = 0; k4 < F_IN / 4; k4++) {
                    float4 v = xv[k4];
                    acc[b] += v.x * w1c[4 * k4 + 0] + v.y * w1c[4 * k4 + 1]
                            + v.z * w1c[4 * k4 + 2] + v.w * w1c[4 * k4 + 3];
                }
            }
            // recurrent contribution
#pragma unroll 4
            for (int k4 = 0; k4 < HU / 4; k4++) {
                float u0 = U1s[(4 * k4 + 0) * G4 + j];
                float u1 = U1s[(4 * k4 + 1) * G4 + j];
                float u2 = U1s[(4 * k4 + 2) * G4 + j];
                float u3 = U1s[(4 * k4 + 3) * G4 + j];
#pragma unroll
                for (int b = 0; b < BB / 2; b++) {
                    float4 hv = *(const float4*)(h1s + (bhalf + b) * HU + 4 * k4);
                    acc[b] += hv.x * u0 + hv.y * u1 + hv.z * u2 + hv.w * u3;
                }
            }
#pragma unroll
            for (int b = 0; b < BB / 2; b++) zs[(bhalf + b) * G4 + j] = acc[b];
        }
        __syncthreads();

        // ---- phase 2: layer-1 state update (i,f,g,o order) ----
        {
            float zi = zs[ub * G4 + uj];
            float zf = zs[ub * G4 + uj + HU];
            float zg = zs[ub * G4 + uj + 2 * HU];
            float zo = zs[ub * G4 + uj + 3 * HU];
            float ig = sigf(zi);
            float fg = sigf(zf);
            float gg = tanhf(zg);
            float og = sigf(zo);
            c1 = fg * c1 + ig * gg;
            h1s[ub * HU + uj] = og * tanhf(c1);
        }
        __syncthreads();

        // ---- phase 3: z2 = h1_t @ W2 + h2 @ U2 + b2 ----
        {
            float acc[BB / 2];
#pragma unroll
            for (int b = 0; b < BB / 2; b++) acc[b] = b2j;

#pragma unroll 4
            for (int k4 = 0; k4 < HU / 4; k4++) {
                float w0 = W2s[(4 * k4 + 0) * G4 + j];
                float w1 = W2s[(4 * k4 + 1) * G4 + j];
                float w2 = W2s[(4 * k4 + 2) * G4 + j];
                float w3 = W2s[(4 * k4 + 3) * G4 + j];
                float u0 = U2s[(4 * k4 + 0) * G4 + j];
                float u1 = U2s[(4 * k4 + 1) * G4 + j];
                float u2 = U2s[(4 * k4 + 2) * G4 + j];
                float u3 = U2s[(4 * k4 + 3) * G4 + j];
#pragma unroll
                for (int b = 0; b < BB / 2; b++) {
                    float4 h1v = *(const float4*)(h1s + (bhalf + b) * HU + 4 * k4);
                    float4 h2v = *(const float4*)(h2s + (bhalf + b) * HU + 4 * k4);
                    acc[b] += h1v.x * w0 + h1v.y * w1 + h1v.z * w2 + h1v.w * w3;
                    acc[b] += h2v.x * u0 + h2v.y * u1 + h2v.z * u2 + h2v.w * u3;
                }
            }
#pragma unroll
            for (int b = 0; b < BB / 2; b++) zs[(bhalf + b) * G4 + j] = acc[b];
        }
        __syncthreads();

        // ---- phase 4: layer-2 state update ----
        {
            float zi = zs[ub * G4 + uj];
            float zf = zs[ub * G4 + uj + HU];
            float zg = zs[ub * G4 + uj + 2 * HU];
            float zo = zs[ub * G4 + uj + 3 * HU];
            float ig = sigf(zi);
            float fg = sigf(zf);
            float gg = tanhf(zg);
            float og = sigf(zo);
            c2 = fg * c2 + ig * gg;
            h2s[ub * HU + uj] = og * tanhf(c2);
        }
        __syncthreads();
    }

    // ---- dense heads: d = sigmoid(h2 @ Wd + bd); out = sigmoid(d @ Wo + bo) ----
    {
        float acc = bd[uj];
#pragma unroll
        for (int k = 0; k < HU; k++) acc += h2s[ub * HU + k] * Wd[k * HU + uj];
        ds[ub * HU + uj] = sigf(acc);
    }
    __syncthreads();
    if (tid < BB) {
        float acc = bo[0];
#pragma unroll
        for (int k = 0; k < HU; k++) acc += ds[tid * HU + k] * Wo[k];
        out[bb0 + tid] = sigf(acc);
    }
}

extern "C" void kernel_launch(void* const* d_in, const int* in_sizes, int n_in,
                              void* d_out, int out_size)
{
    const float* x  = (const float*)d_in[0];
    const float* W1 = (const float*)d_in[1];
    const float* U1 = (const float*)d_in[2];
    const float* b1 = (const float*)d_in[3];
    const float* W2 = (const float*)d_in[4];
    const float* U2 = (const float*)d_in[5];
    const float* b2 = (const float*)d_in[6];
    const float* Wd = (const float*)d_in[7];
    const float* bd = (const float*)d_in[8];
    const float* Wo = (const float*)d_in[9];
    const float* bo = (const float*)d_in[10];
    float* out = (float*)d_out;

    const int B = 4096;
    const size_t smem_bytes =
        (size_t)(3 * HU * G4 + BB * G4 + 2 * BB * HU + BB * F_IN + BB * HU) * sizeof(float);

    cudaFuncSetAttribute(lstm_fused_kernel,
                         cudaFuncAttributeMaxDynamicSharedMemorySize,
                         (int)smem_bytes);

    dim3 grid(B / BB);
    dim3 block(NTH);
    lstm_fused_kernel<<<grid, block, smem_bytes>>>(x, W1, U1, b1, W2, U2, b2,
                                                   Wd, bd, Wo, bo, out);
}